// round 14
// baseline (speedup 1.0000x reference)
#include <cuda_runtime.h>
#include <math.h>
#include <stdint.h>

#define S_LEN 3744
#define DIM 1536
#define NH 12
#define HD 128
#define HH 26
#define WW 48
#define EPSN 1e-6f

// scratch (allocation-free rule: __device__ globals)
__device__ float g_q[S_LEN * DIM];
__device__ float g_k[S_LEN * DIM];
__device__ float g_v[S_LEN * DIM];
__device__ float g_o[S_LEN * DIM];
__device__ float g_x[S_LEN * DIM];        // tf32-rounded x
__device__ float g_wq[DIM * DIM];         // tf32-rounded weights
__device__ float g_wk[DIM * DIM];
__device__ float g_wv[DIM * DIM];
__device__ float g_wo[DIM * DIM];

// ---------------------------------------------------------------------------
// helpers
// ---------------------------------------------------------------------------
__device__ __forceinline__ uint32_t f2tf(float x) {
    uint32_t u;
    asm("cvt.rna.tf32.f32 %0, %1;" : "=r"(u) : "f"(x));
    return u;
}

__device__ __forceinline__ void mma8(
    float& c0, float& c1, float& c2, float& c3,
    uint32_t a0, uint32_t a1, uint32_t a2, uint32_t a3,
    uint32_t b0, uint32_t b1)
{
    asm volatile(
        "mma.sync.aligned.m16n8k8.row.col.f32.tf32.tf32.f32 "
        "{%0,%1,%2,%3}, {%4,%5,%6,%7}, {%8,%9}, {%0,%1,%2,%3};\n"
        : "+f"(c0), "+f"(c1), "+f"(c2), "+f"(c3)
        : "r"(a0), "r"(a1), "r"(a2), "r"(a3), "r"(b0), "r"(b1));
}

__device__ __forceinline__ void cp16(uint32_t dst_smem, const void* src, int srcsz) {
    asm volatile("cp.async.ca.shared.global [%0], [%1], 16, %2;\n"
                 :: "r"(dst_smem), "l"(src), "r"(srcsz));
}
#define CP_COMMIT() asm volatile("cp.async.commit_group;\n")
#define CP_WAIT0()  asm volatile("cp.async.wait_group 0;\n")
#define CP_WAIT1()  asm volatile("cp.async.wait_group 1;\n")

__device__ __forceinline__ uint32_t smem_u32(const void* p) {
    return (uint32_t)__cvta_generic_to_shared(p);
}

// ---------------------------------------------------------------------------
// fused pre-round: 5 tensors, flattened linear index, tf32_rna
// ---------------------------------------------------------------------------
#define NX4 (S_LEN * DIM / 4)
#define NW4 (DIM * DIM / 4)

__global__ __launch_bounds__(256) void pre_round5(
    const float* __restrict__ x,  float* __restrict__ xo,
    const float* __restrict__ w0, float* __restrict__ w0o,
    const float* __restrict__ w1, float* __restrict__ w1o,
    const float* __restrict__ w2, float* __restrict__ w2o,
    const float* __restrict__ w3, float* __restrict__ w3o)
{
    int i = blockIdx.x * 256 + threadIdx.x;
    const float* in; float* out; int j;
    if (i < NX4)                { in = x;  out = xo;  j = i; }
    else if ((i -= NX4) < NW4)  { in = w0; out = w0o; j = i; }
    else if ((i -= NW4) < NW4)  { in = w1; out = w1o; j = i; }
    else if ((i -= NW4) < NW4)  { in = w2; out = w2o; j = i; }
    else if ((i -= NW4) < NW4)  { in = w3; out = w3o; j = i; }
    else return;
    float4 v = ((const float4*)in)[j];
    float4 r;
    r.x = __uint_as_float(f2tf(v.x));
    r.y = __uint_as_float(f2tf(v.y));
    r.z = __uint_as_float(f2tf(v.z));
    r.w = __uint_as_float(f2tf(v.w));
    ((float4*)out)[j] = r;
}
#define PR_TOTAL (NX4 + 4 * NW4)

// ---------------------------------------------------------------------------
// tf32 GEMM, cp.async 2-stage, 128x128 block, 128 threads (4 warps of 64x64).
// ---------------------------------------------------------------------------
#define GBK 16
#define GAS 20

__global__ __launch_bounds__(128) void gemm_nt_tf32(
    const float* __restrict__ A,
    const float* __restrict__ w0, const float* __restrict__ w1, const float* __restrict__ w2,
    const float* __restrict__ b0p, const float* __restrict__ b1p, const float* __restrict__ b2p,
    float* __restrict__ c0p, float* __restrict__ c1p, float* __restrict__ c2p,
    int M, int N, int K, int round_out)
{
    __shared__ uint32_t As[2][128 * GAS];
    __shared__ uint32_t Bs[2][128 * GAS];

    const int z = blockIdx.z;
    const float* Bw   = (z == 0) ? w0 : (z == 1) ? w1 : w2;
    const float* bias = (z == 0) ? b0p : (z == 1) ? b1p : b2p;
    float* C          = (z == 0) ? c0p : (z == 1) ? c1p : c2p;

    const int tid = threadIdx.x;
    const int lane = tid & 31;
    const int wid = tid >> 5;          // 0..3
    const int g = lane >> 2;
    const int t = lane & 3;
    const int bm = blockIdx.y * 128;
    const int bn = blockIdx.x * 128;
    const int warp_m = (wid >> 1) * 64;
    const int warp_n = (wid & 1) * 64;

    float acc[4][8][4];
#pragma unroll
    for (int a = 0; a < 4; a++)
#pragma unroll
        for (int b = 0; b < 8; b++)
#pragma unroll
            for (int c = 0; c < 4; c++) acc[a][b][c] = 0.f;

    auto issue = [&](int st, int kt) {
#pragma unroll
        for (int u = 0; u < 4; u++) {
            int slot = tid + 128 * u;
            int r = slot >> 2;
            int q = (slot & 3) * 4;
            int asz = (bm + r) < M ? 16 : 0;
            cp16(smem_u32(&As[st][r * GAS + q]), A + (size_t)(bm + r) * K + kt + q, asz);
            cp16(smem_u32(&Bs[st][r * GAS + q]), Bw + (size_t)(bn + r) * K + kt + q, 16);
        }
    };

    issue(0, 0);
    CP_COMMIT();

    int st = 0;
    for (int kt = 0; kt < K; kt += GBK, st ^= 1) {
        CP_WAIT0();
        __syncthreads();
        if (kt + GBK < K) {
            issue(st ^ 1, kt + GBK);
            CP_COMMIT();
        }

#pragma unroll
        for (int ks = 0; ks < 2; ks++) {
            const int c = ks * 8 + t;
            uint32_t af[4][4];
#pragma unroll
            for (int mt = 0; mt < 4; mt++) {
                int row = warp_m + mt * 16 + g;
                af[mt][0] = As[st][row * GAS + c];
                af[mt][1] = As[st][(row + 8) * GAS + c];
                af[mt][2] = As[st][row * GAS + c + 4];
                af[mt][3] = As[st][(row + 8) * GAS + c + 4];
            }
            uint32_t bf[8][2];
#pragma unroll
            for (int nt = 0; nt < 8; nt++) {
                int n = warp_n + nt * 8 + g;
                bf[nt][0] = Bs[st][n * GAS + c];
                bf[nt][1] = Bs[st][n * GAS + c + 4];
            }
#pragma unroll
            for (int mt = 0; mt < 4; mt++)
#pragma unroll
                for (int nt = 0; nt < 8; nt++)
                    mma8(acc[mt][nt][0], acc[mt][nt][1], acc[mt][nt][2], acc[mt][nt][3],
                         af[mt][0], af[mt][1], af[mt][2], af[mt][3],
                         bf[nt][0], bf[nt][1]);
        }
        __syncthreads();
    }

#pragma unroll
    for (int mt = 0; mt < 4; mt++) {
        int row0 = bm + warp_m + mt * 16 + g;
#pragma unroll
        for (int nt = 0; nt < 8; nt++) {
            int col = bn + warp_n + nt * 8 + t * 2;
            float bb0 = bias[col], bb1 = bias[col + 1];
            float e00 = acc[mt][nt][0] + bb0, e01 = acc[mt][nt][1] + bb1;
            float e10 = acc[mt][nt][2] + bb0, e11 = acc[mt][nt][3] + bb1;
            if (round_out) {
                e00 = __uint_as_float(f2tf(e00));
                e01 = __uint_as_float(f2tf(e01));
                e10 = __uint_as_float(f2tf(e10));
                e11 = __uint_as_float(f2tf(e11));
            }
            if (row0 < M)
                *(float2*)(C + (size_t)row0 * N + col) = make_float2(e00, e01);
            if (row0 + 8 < M)
                *(float2*)(C + (size_t)(row0 + 8) * N + col) = make_float2(e10, e11);
        }
    }
}

// ---------------------------------------------------------------------------
// Fused RMSNorm + 3D RoPE (angles fp64, first principles), tf32-rounded store.
// ---------------------------------------------------------------------------
__global__ __launch_bounds__(256) void rmsrope_kernel(
    float* __restrict__ q, float* __restrict__ k,
    const float* __restrict__ gq, const float* __restrict__ gk)
{
    const int s = blockIdx.x;
    const int tid = threadIdx.x;
    float* qr = q + (size_t)s * DIM;
    float* kr = k + (size_t)s * DIM;

    float sq = 0.f, sk = 0.f;
    for (int i = tid; i < DIM; i += 256) {
        float a = qr[i]; sq = fmaf(a, a, sq);
        float b = kr[i]; sk = fmaf(b, b, sk);
    }
    __shared__ float bq_[256], bk_[256];
    bq_[tid] = sq; bk_[tid] = sk;
    __syncthreads();
    for (int off = 128; off > 0; off >>= 1) {
        if (tid < off) { bq_[tid] += bq_[tid + off]; bk_[tid] += bk_[tid + off]; }
        __syncthreads();
    }
    const float rq = rsqrtf(bq_[0] * (1.0f / DIM) + EPSN);
    const float rk = rsqrtf(bk_[0] * (1.0f / DIM) + EPSN);

    const int f = s / (HH * WW);
    const int rem = s - f * (HH * WW);
    const int hp = rem / WW;
    const int wp = rem - hp * WW;

#pragma unroll
    for (int u = 0; u < 3; u++) {
        int p = tid + u * 256;
        int h = p >> 6;
        int c = p & 63;
        int pos, j, dim;
        if (c < 22)      { pos = f;  j = c;      dim = 44; }
        else if (c < 43) { pos = hp; j = c - 22; dim = 42; }
        else             { pos = wp; j = c - 43; dim = 42; }
        double inv = pow(10000.0, -2.0 * (double)j / (double)dim);
        double ang = (double)pos * inv;
        double sd, cd;
        sincos(ang, &sd, &cd);
        float cs = (float)cd, sn = (float)sd;

        int base = h * HD + 2 * c;
        float q0 = qr[base] * rq * gq[base];
        float q1 = qr[base + 1] * rq * gq[base + 1];
        qr[base]     = __uint_as_float(f2tf(q0 * cs - q1 * sn));
        qr[base + 1] = __uint_as_float(f2tf(q0 * sn + q1 * cs));
        float k0 = kr[base] * rk * gk[base];
        float k1 = kr[base + 1] * rk * gk[base + 1];
        kr[base]     = __uint_as_float(f2tf(k0 * cs - k1 * sn));
        kr[base + 1] = __uint_as_float(f2tf(k0 * sn + k1 * cs));
    }
}

// ---------------------------------------------------------------------------
// Flash attention v3 (fixed): Q fragments in registers, cp.async
// single-buffered K/V pipelined across chunk phases, 2 CTAs/SM (16 warps).
// Fill mapping: 64 rows x 128 floats = 2048 float4 slots -> 8 per thread.
// ---------------------------------------------------------------------------
#define QT 64
#define KVS 132
#define PSS 68
#define SM_K 0
#define SM_V (QT * KVS)
#define SM_P (2 * QT * KVS)
#define SM_RED (SM_P + QT * PSS)
#define FL_U32 (SM_RED + 3 * QT)
#define FL_SMEM_BYTES (FL_U32 * 4)

__global__ __launch_bounds__(256, 2) void flash_tf32(
    const float* __restrict__ q, const float* __restrict__ k,
    const float* __restrict__ v, float* __restrict__ o,
    const int* __restrict__ seq_lens)
{
    extern __shared__ uint32_t smu[];
    uint32_t* Ks = smu + SM_K;
    uint32_t* Vs = smu + SM_V;
    float* Ps   = (float*)(smu + SM_P);
    float* mrow = (float*)(smu + SM_RED);
    float* lrow = mrow + QT;
    float* arow = lrow + QT;
    const uint32_t sbase = smem_u32(smu);

    const int tid = threadIdx.x;
    const int lane = tid & 31;
    const int wid = tid >> 5;
    const int g = lane >> 2;
    const int t = lane & 3;
    const int head = blockIdx.y;
    const int q0 = blockIdx.x * QT;
    const int seqlen = seq_lens[0];
    const int hoff = head * HD;
    const int nch = (seqlen + 63) >> 6;

    // S-phase: 4m x 2n (warp tile 16x32). O-phase: 2m x 4n (warp tile 32x32).
    const int wm_s = (wid >> 1) * 16;
    const int wn_s = (wid & 1) * 32;
    const int wm_o = (wid >> 2) * 32;
    const int wn_o = (wid & 3) * 32;

    // cp.async tile fills: 2048 float4 slots / 256 threads = 8 per thread
    auto issueK = [&](int c) {
        int kv0 = c * 64;
#pragma unroll
        for (int u = 0; u < 8; u++) {
            int slot = tid + 256 * u;
            int r = slot >> 5;
            int qq = (slot & 31) * 4;
            int gr = kv0 + r;
            int sz = (gr < seqlen) ? 16 : 0;
            const float* src = k + (size_t)(sz ? gr : 0) * DIM + hoff + qq;
            cp16(sbase + (SM_K + r * KVS + qq) * 4, src, sz);
        }
    };
    auto issueV = [&](int c) {
        int kv0 = c * 64;
#pragma unroll
        for (int u = 0; u < 8; u++) {
            int slot = tid + 256 * u;
            int r = slot >> 5;
            int qq = (slot & 31) * 4;
            int gr = kv0 + r;
            int sz = (gr < seqlen) ? 16 : 0;
            const float* src = v + (size_t)(sz ? gr : 0) * DIM + hoff + qq;
            cp16(sbase + (SM_V + r * KVS + qq) * 4, src, sz);
        }
    };

    issueK(0); CP_COMMIT();
    issueV(0); CP_COMMIT();

    // Q fragments in registers (loop-invariant); q is pre-rounded tf32 bits.
    uint32_t qf[16][4];
    {
        int r0 = q0 + wm_s + g;
        const float* qp0 = q + (size_t)r0 * DIM + hoff;
        const float* qp1 = qp0 + (size_t)8 * DIM;
        bool v0 = r0 < S_LEN, v1 = (r0 + 8) < S_LEN;
#pragma unroll
        for (int ks = 0; ks < 16; ks++) {
            int c = ks * 8 + t;
            qf[ks][0] = v0 ? __float_as_uint(qp0[c]) : 0u;
            qf[ks][1] = v1 ? __float_as_uint(qp1[c]) : 0u;
            qf[ks][2] = v0 ? __float_as_uint(qp0[c + 4]) : 0u;
            qf[ks][3] = v1 ? __float_as_uint(qp1[c + 4]) : 0u;
        }
    }
    if (tid < QT) { mrow[tid] = -3.0e38f; lrow[tid] = 0.f; }

    float oacc[2][4][4];
#pragma unroll
    for (int a = 0; a < 2; a++)
#pragma unroll
        for (int b = 0; b < 4; b++)
#pragma unroll
            for (int c = 0; c < 4; c++) oacc[a][b][c] = 0.f;

    const float scale = 0.08838834764831845f;

    for (int c = 0; c < nch; c++) {
        const int kv0 = c * 64;
        CP_WAIT1();          // K(c) ready (V(c) may still be in flight)
        __syncthreads();

        // ---------- S = Q @ K^T : per-warp 16x32, A from registers ----------
        float sacc[4][4];
#pragma unroll
        for (int a = 0; a < 4; a++)
#pragma unroll
            for (int b = 0; b < 4; b++) sacc[a][b] = 0.f;

#pragma unroll
        for (int ks = 0; ks < 16; ks++) {
            const int cc = ks * 8 + t;
            uint32_t b0[4], b1[4];
#pragma unroll
            for (int nt = 0; nt < 4; nt++) {
                int n = wn_s + nt * 8 + g;
                b0[nt] = Ks[n * KVS + cc];
                b1[nt] = Ks[n * KVS + cc + 4];
            }
#pragma unroll
            for (int nt = 0; nt < 4; nt++)
                mma8(sacc[nt][0], sacc[nt][1], sacc[nt][2], sacc[nt][3],
                     qf[ks][0], qf[ks][1], qf[ks][2], qf[ks][3],
                     b0[nt], b1[nt]);
        }

        // write scaled+masked scores
        {
            int row = wm_s + g;
#pragma unroll
            for (int nt = 0; nt < 4; nt++) {
                int col = wn_s + nt * 8 + 2 * t;
                bool m0 = (kv0 + col) >= seqlen;
                bool m1 = (kv0 + col + 1) >= seqlen;
                float2 v0 = make_float2(m0 ? -1e30f : sacc[nt][0] * scale,
                                        m1 ? -1e30f : sacc[nt][1] * scale);
                float2 v1 = make_float2(m0 ? -1e30f : sacc[nt][2] * scale,
                                        m1 ? -1e30f : sacc[nt][3] * scale);
                *(float2*)(Ps + row * PSS + col) = v0;
                *(float2*)(Ps + (row + 8) * PSS + col) = v1;
            }
        }
        __syncthreads();     // S-phase done reading K; P visible

        if (c + 1 < nch) { issueK(c + 1); CP_COMMIT(); }

        // ---------- online softmax (4 threads/row) ----------
        {
            const int i = tid >> 2, sub = tid & 3;
            const int jbase = sub * 16;
            float mold = mrow[i];
            float mloc = -3.0e38f;
#pragma unroll
            for (int jj = 0; jj < 16; jj++)
                mloc = fmaxf(mloc, Ps[i * PSS + jbase + jj]);
            mloc = fmaxf(mloc, __shfl_xor_sync(0xffffffffu, mloc, 1));
            mloc = fmaxf(mloc, __shfl_xor_sync(0xffffffffu, mloc, 2));
            float mnew = fmaxf(mold, mloc);
            float sum = 0.f;
#pragma unroll
            for (int jj = 0; jj < 16; jj++) {
                float p = __expf(Ps[i * PSS + jbase + jj] - mnew);
                Ps[i * PSS + jbase + jj] = p;
                sum += p;
            }
            sum += __shfl_xor_sync(0xffffffffu, sum, 1);
            sum += __shfl_xor_sync(0xffffffffu, sum, 2);
            if (sub == 0) {
                float al = __expf(mold - mnew);
                arow[i] = al;
                lrow[i] = lrow[i] * al + sum;
                mrow[i] = mnew;
            }
        }

        if (c + 1 < nch) { CP_WAIT1(); } else { CP_WAIT0(); }  // V(c) ready
        __syncthreads();     // softmax P/arow visible; V(c) visible

        // ---------- O = alpha*O + P @ V : per-warp 32x32 ----------
#pragma unroll
        for (int mt = 0; mt < 2; mt++) {
            int row = wm_o + mt * 16 + g;
            float al0 = arow[row];
            float al1 = arow[row + 8];
#pragma unroll
            for (int nt = 0; nt < 4; nt++) {
                oacc[mt][nt][0] *= al0;
                oacc[mt][nt][1] *= al0;
                oacc[mt][nt][2] *= al1;
                oacc[mt][nt][3] *= al1;
            }
        }
#pragma unroll
        for (int ks = 0; ks < 8; ks++) {
            const int cc = ks * 8 + t;
            uint32_t paf[2][4];
#pragma unroll
            for (int mt = 0; mt < 2; mt++) {
                int row = wm_o + mt * 16 + g;
                paf[mt][0] = __float_as_uint(Ps[row * PSS + cc]);
                paf[mt][1] = __float_as_uint(Ps[(row + 8) * PSS + cc]);
                paf[mt][2] = __float_as_uint(Ps[row * PSS + cc + 4]);
                paf[mt][3] = __float_as_uint(Ps[(row + 8) * PSS + cc + 4]);
            }
#pragma unroll
            for (int nt = 0; nt < 4; nt++) {
                int n = wn_o + nt * 8 + g;
                uint32_t vb0 = Vs[cc * KVS + n];
                uint32_t vb1 = Vs[(cc + 4) * KVS + n];
#pragma unroll
                for (int mt = 0; mt < 2; mt++)
                    mma8(oacc[mt][nt][0], oacc[mt][nt][1], oacc[mt][nt][2], oacc[mt][nt][3],
                         paf[mt][0], paf[mt][1], paf[mt][2], paf[mt][3], vb0, vb1);
            }
        }
        __syncthreads();     // O-phase done reading V(c)
        if (c + 1 < nch) { issueV(c + 1); CP_COMMIT(); }
    }

    // epilogue: divide by l, tf32-round, store
#pragma unroll
    for (int mt = 0; mt < 2; mt++) {
        int lr0 = wm_o + mt * 16 + g;
        int grow0 = q0 + lr0;
        float inv0 = 1.0f / lrow[lr0];
        float inv1 = 1.0f / lrow[lr0 + 8];
#pragma unroll
        for (int nt = 0; nt < 4; nt++) {
            int col = hoff + wn_o + nt * 8 + t * 2;
            if (grow0 < S_LEN) {
                float2 v0 = make_float2(
                    __uint_as_float(f2tf(oacc[mt][nt][0] * inv0)),
                    __uint_as_float(f2tf(oacc[mt][nt][1] * inv0)));
                *(float2*)(o + (size_t)grow0 * DIM + col) = v0;
            }
            if (grow0 + 8 < S_LEN) {
                float2 v1 = make_float2(
                    __uint_as_float(f2tf(oacc[mt][nt][2] * inv1)),
                    __uint_as_float(f2tf(oacc[mt][nt][3] * inv1)));
                *(float2*)(o + (size_t)(grow0 + 8) * DIM + col) = v1;
            }
        }
    }
}

// ---------------------------------------------------------------------------
extern "C" void kernel_launch(void* const* d_in, const int* in_sizes, int n_in,
                              void* d_out, int out_size)
{
    const float* x  = (const float*)d_in[0];
    const float* wq = (const float*)d_in[1];
    const float* bq = (const float*)d_in[2];
    const float* wk = (const float*)d_in[3];
    const float* bk = (const float*)d_in[4];
    const float* wv = (const float*)d_in[5];
    const float* bv = (const float*)d_in[6];
    const float* wo = (const float*)d_in[7];
    const float* bo = (const float*)d_in[8];
    const float* gq = (const float*)d_in[9];
    const float* gk = (const float*)d_in[10];
    const int* seq_lens = (const int*)d_in[12];
    float* out = (float*)d_out;

    float *qp, *kp, *vp, *op, *xp, *wqp, *wkp, *wvp, *wop;
    cudaGetSymbolAddress((void**)&qp, g_q);
    cudaGetSymbolAddress((void**)&kp, g_k);
    cudaGetSymbolAddress((void**)&vp, g_v);
    cudaGetSymbolAddress((void**)&op, g_o);
    cudaGetSymbolAddress((void**)&xp, g_x);
    cudaGetSymbolAddress((void**)&wqp, g_wq);
    cudaGetSymbolAddress((void**)&wkp, g_wk);
    cudaGetSymbolAddress((void**)&wvp, g_wv);
    cudaGetSymbolAddress((void**)&wop, g_wo);

    // fused pre-round of x + 4 weights
    pre_round5<<<(PR_TOTAL + 255) / 256, 256>>>(x, xp, wq, wqp, wk, wkp,
                                                wv, wvp, wo, wop);

    // fused Q/K/V projections (tf32-rounded outputs)
    dim3 gqkv(DIM / 128, (S_LEN + 127) / 128, 3);
    gemm_nt_tf32<<<gqkv, 128>>>(xp, wqp, wkp, wvp, bq, bk, bv, qp, kp, vp,
                                S_LEN, DIM, DIM, 1);

    rmsrope_kernel<<<S_LEN, 256>>>(qp, kp, gq, gk);

    cudaFuncSetAttribute(flash_tf32, cudaFuncAttributeMaxDynamicSharedMemorySize,
                         FL_SMEM_BYTES);
    flash_tf32<<<dim3((S_LEN + QT - 1) / QT, NH), 256, FL_SMEM_BYTES>>>(
        qp, kp, vp, op, seq_lens);

    // output projection (fp32 output)
    dim3 go(DIM / 128, (S_LEN + 127) / 128, 1);
    gemm_nt_tf32<<<go, 128>>>(op, wop, wop, wop, bo, bo, bo, out, out, out,
                              S_LEN, DIM, DIM, 0);
}

// round 15
// speedup vs baseline: 1.5768x; 1.5768x over previous
#include <cuda_runtime.h>
#include <math.h>
#include <stdint.h>

#define S_LEN 3744
#define DIM 1536
#define NH 12
#define HD 128
#define HH 26
#define WW 48
#define EPSN 1e-6f

// scratch (allocation-free rule: __device__ globals)
__device__ float g_q[S_LEN * DIM];
__device__ float g_k[S_LEN * DIM];
__device__ float g_v[S_LEN * DIM];
__device__ float g_o[S_LEN * DIM];
__device__ float g_x[S_LEN * DIM];        // tf32-rounded x
__device__ float g_wq[DIM * DIM];         // tf32-rounded weights
__device__ float g_wk[DIM * DIM];
__device__ float g_wv[DIM * DIM];
__device__ float g_wo[DIM * DIM];

// ---------------------------------------------------------------------------
// helpers
// ---------------------------------------------------------------------------
__device__ __forceinline__ uint32_t f2tf(float x) {
    uint32_t u;
    asm("cvt.rna.tf32.f32 %0, %1;" : "=r"(u) : "f"(x));
    return u;
}

__device__ __forceinline__ void mma8(
    float& c0, float& c1, float& c2, float& c3,
    uint32_t a0, uint32_t a1, uint32_t a2, uint32_t a3,
    uint32_t b0, uint32_t b1)
{
    asm volatile(
        "mma.sync.aligned.m16n8k8.row.col.f32.tf32.tf32.f32 "
        "{%0,%1,%2,%3}, {%4,%5,%6,%7}, {%8,%9}, {%0,%1,%2,%3};\n"
        : "+f"(c0), "+f"(c1), "+f"(c2), "+f"(c3)
        : "r"(a0), "r"(a1), "r"(a2), "r"(a3), "r"(b0), "r"(b1));
}

__device__ __forceinline__ void cp16(uint32_t dst_smem, const void* src, int srcsz) {
    asm volatile("cp.async.ca.shared.global [%0], [%1], 16, %2;\n"
                 :: "r"(dst_smem), "l"(src), "r"(srcsz));
}
#define CP_COMMIT() asm volatile("cp.async.commit_group;\n")
#define CP_WAIT0()  asm volatile("cp.async.wait_group 0;\n")

__device__ __forceinline__ uint32_t smem_u32(const void* p) {
    return (uint32_t)__cvta_generic_to_shared(p);
}

// ---------------------------------------------------------------------------
// fused pre-round: 5 tensors, flattened linear index, tf32_rna
// ---------------------------------------------------------------------------
#define NX4 (S_LEN * DIM / 4)
#define NW4 (DIM * DIM / 4)

__global__ __launch_bounds__(256) void pre_round5(
    const float* __restrict__ x,  float* __restrict__ xo,
    const float* __restrict__ w0, float* __restrict__ w0o,
    const float* __restrict__ w1, float* __restrict__ w1o,
    const float* __restrict__ w2, float* __restrict__ w2o,
    const float* __restrict__ w3, float* __restrict__ w3o)
{
    int i = blockIdx.x * 256 + threadIdx.x;
    const float* in; float* out; int j;
    if (i < NX4)                { in = x;  out = xo;  j = i; }
    else if ((i -= NX4) < NW4)  { in = w0; out = w0o; j = i; }
    else if ((i -= NW4) < NW4)  { in = w1; out = w1o; j = i; }
    else if ((i -= NW4) < NW4)  { in = w2; out = w2o; j = i; }
    else if ((i -= NW4) < NW4)  { in = w3; out = w3o; j = i; }
    else return;
    float4 v = ((const float4*)in)[j];
    float4 r;
    r.x = __uint_as_float(f2tf(v.x));
    r.y = __uint_as_float(f2tf(v.y));
    r.z = __uint_as_float(f2tf(v.z));
    r.w = __uint_as_float(f2tf(v.w));
    ((float4*)out)[j] = r;
}
#define PR_TOTAL (NX4 + 4 * NW4)

// ---------------------------------------------------------------------------
// tf32 GEMM: BK=32, cp.async 2-stage (dynamic smem), 128x128 block,
// 128 threads (4 warps of 64x64). GAS=36 -> conflict-free frags.
// ---------------------------------------------------------------------------
#define GBK 32
#define GAS 36
#define GSTAGE (128 * GAS)
#define G_SMEM_BYTES (4 * GSTAGE * 4)

__global__ __launch_bounds__(128) void gemm_nt_tf32(
    const float* __restrict__ A,
    const float* __restrict__ w0, const float* __restrict__ w1, const float* __restrict__ w2,
    const float* __restrict__ b0p, const float* __restrict__ b1p, const float* __restrict__ b2p,
    float* __restrict__ c0p, float* __restrict__ c1p, float* __restrict__ c2p,
    int M, int N, int K, int round_out)
{
    extern __shared__ uint32_t gsm[];
    uint32_t* Asm = gsm;                 // [2][GSTAGE]
    uint32_t* Bsm = gsm + 2 * GSTAGE;    // [2][GSTAGE]

    const int z = blockIdx.z;
    const float* Bw   = (z == 0) ? w0 : (z == 1) ? w1 : w2;
    const float* bias = (z == 0) ? b0p : (z == 1) ? b1p : b2p;
    float* C          = (z == 0) ? c0p : (z == 1) ? c1p : c2p;

    const int tid = threadIdx.x;
    const int lane = tid & 31;
    const int wid = tid >> 5;          // 0..3
    const int g = lane >> 2;
    const int t = lane & 3;
    const int bm = blockIdx.y * 128;
    const int bn = blockIdx.x * 128;
    const int warp_m = (wid >> 1) * 64;
    const int warp_n = (wid & 1) * 64;

    float acc[4][8][4];
#pragma unroll
    for (int a = 0; a < 4; a++)
#pragma unroll
        for (int b = 0; b < 8; b++)
#pragma unroll
            for (int c = 0; c < 4; c++) acc[a][b][c] = 0.f;

    // fill: 128 rows x 32 floats = 1024 float4 slots per matrix, 8 per thread
    auto issue = [&](int st, int kt) {
        uint32_t abase = smem_u32(Asm + st * GSTAGE);
        uint32_t bbase = smem_u32(Bsm + st * GSTAGE);
#pragma unroll
        for (int u = 0; u < 8; u++) {
            int slot = tid + 128 * u;
            int r = slot >> 3;
            int q = (slot & 7) * 4;
            int asz = (bm + r) < M ? 16 : 0;
            cp16(abase + (r * GAS + q) * 4, A + (size_t)(bm + r) * K + kt + q, asz);
            cp16(bbase + (r * GAS + q) * 4, Bw + (size_t)(bn + r) * K + kt + q, 16);
        }
    };

    issue(0, 0);
    CP_COMMIT();

    int st = 0;
    for (int kt = 0; kt < K; kt += GBK, st ^= 1) {
        CP_WAIT0();
        __syncthreads();
        if (kt + GBK < K) {
            issue(st ^ 1, kt + GBK);
            CP_COMMIT();
        }
        const uint32_t* As = Asm + st * GSTAGE;
        const uint32_t* Bs = Bsm + st * GSTAGE;

#pragma unroll
        for (int ks = 0; ks < 4; ks++) {
            const int c = ks * 8 + t;
            uint32_t af[4][4];
#pragma unroll
            for (int mt = 0; mt < 4; mt++) {
                int row = warp_m + mt * 16 + g;
                af[mt][0] = As[row * GAS + c];
                af[mt][1] = As[(row + 8) * GAS + c];
                af[mt][2] = As[row * GAS + c + 4];
                af[mt][3] = As[(row + 8) * GAS + c + 4];
            }
            uint32_t bf[8][2];
#pragma unroll
            for (int nt = 0; nt < 8; nt++) {
                int n = warp_n + nt * 8 + g;
                bf[nt][0] = Bs[n * GAS + c];
                bf[nt][1] = Bs[n * GAS + c + 4];
            }
#pragma unroll
            for (int mt = 0; mt < 4; mt++)
#pragma unroll
                for (int nt = 0; nt < 8; nt++)
                    mma8(acc[mt][nt][0], acc[mt][nt][1], acc[mt][nt][2], acc[mt][nt][3],
                         af[mt][0], af[mt][1], af[mt][2], af[mt][3],
                         bf[nt][0], bf[nt][1]);
        }
        __syncthreads();
    }

#pragma unroll
    for (int mt = 0; mt < 4; mt++) {
        int row0 = bm + warp_m + mt * 16 + g;
#pragma unroll
        for (int nt = 0; nt < 8; nt++) {
            int col = bn + warp_n + nt * 8 + t * 2;
            float bb0 = bias[col], bb1 = bias[col + 1];
            float e00 = acc[mt][nt][0] + bb0, e01 = acc[mt][nt][1] + bb1;
            float e10 = acc[mt][nt][2] + bb0, e11 = acc[mt][nt][3] + bb1;
            if (round_out) {
                e00 = __uint_as_float(f2tf(e00));
                e01 = __uint_as_float(f2tf(e01));
                e10 = __uint_as_float(f2tf(e10));
                e11 = __uint_as_float(f2tf(e11));
            }
            if (row0 < M)
                *(float2*)(C + (size_t)row0 * N + col) = make_float2(e00, e01);
            if (row0 + 8 < M)
                *(float2*)(C + (size_t)(row0 + 8) * N + col) = make_float2(e10, e11);
        }
    }
}

// ---------------------------------------------------------------------------
// Fused RMSNorm + 3D RoPE (angles fp64, first principles), tf32-rounded store.
// ---------------------------------------------------------------------------
__global__ __launch_bounds__(256) void rmsrope_kernel(
    float* __restrict__ q, float* __restrict__ k,
    const float* __restrict__ gq, const float* __restrict__ gk)
{
    const int s = blockIdx.x;
    const int tid = threadIdx.x;
    float* qr = q + (size_t)s * DIM;
    float* kr = k + (size_t)s * DIM;

    float sq = 0.f, sk = 0.f;
    for (int i = tid; i < DIM; i += 256) {
        float a = qr[i]; sq = fmaf(a, a, sq);
        float b = kr[i]; sk = fmaf(b, b, sk);
    }
    __shared__ float bq_[256], bk_[256];
    bq_[tid] = sq; bk_[tid] = sk;
    __syncthreads();
    for (int off = 128; off > 0; off >>= 1) {
        if (tid < off) { bq_[tid] += bq_[tid + off]; bk_[tid] += bk_[tid + off]; }
        __syncthreads();
    }
    const float rq = rsqrtf(bq_[0] * (1.0f / DIM) + EPSN);
    const float rk = rsqrtf(bk_[0] * (1.0f / DIM) + EPSN);

    const int f = s / (HH * WW);
    const int rem = s - f * (HH * WW);
    const int hp = rem / WW;
    const int wp = rem - hp * WW;

#pragma unroll
    for (int u = 0; u < 3; u++) {
        int p = tid + u * 256;
        int h = p >> 6;
        int c = p & 63;
        int pos, j, dim;
        if (c < 22)      { pos = f;  j = c;      dim = 44; }
        else if (c < 43) { pos = hp; j = c - 22; dim = 42; }
        else             { pos = wp; j = c - 43; dim = 42; }
        double inv = pow(10000.0, -2.0 * (double)j / (double)dim);
        double ang = (double)pos * inv;
        double sd, cd;
        sincos(ang, &sd, &cd);
        float cs = (float)cd, sn = (float)sd;

        int base = h * HD + 2 * c;
        float q0 = qr[base] * rq * gq[base];
        float q1 = qr[base + 1] * rq * gq[base + 1];
        qr[base]     = __uint_as_float(f2tf(q0 * cs - q1 * sn));
        qr[base + 1] = __uint_as_float(f2tf(q0 * sn + q1 * cs));
        float k0 = kr[base] * rk * gk[base];
        float k1 = kr[base + 1] * rk * gk[base + 1];
        kr[base]     = __uint_as_float(f2tf(k0 * cs - k1 * sn));
        kr[base + 1] = __uint_as_float(f2tf(k0 * sn + k1 * cs));
    }
}

// ---------------------------------------------------------------------------
// Flash attention (reverted to the measured-840us R11/R12 version:
// 64 q-rows/block, 256 threads, 2 CTA/SM, shared K/V smem tile,
// register-prefetched KV).
// ---------------------------------------------------------------------------
#define QT 64
#define QKS 132
#define PSS 68
#define FL_SMEM_U32 (2 * QT * QKS + QT * PSS + 3 * QT)
#define FL_SMEM_BYTES (FL_SMEM_U32 * 4)

__global__ __launch_bounds__(256, 2) void flash_tf32(
    const float* __restrict__ q, const float* __restrict__ k,
    const float* __restrict__ v, float* __restrict__ o,
    const int* __restrict__ seq_lens)
{
    extern __shared__ uint32_t smu[];
    uint32_t* Qs  = smu;
    uint32_t* KVs = Qs + QT * QKS;
    float* Ps   = (float*)(KVs + QT * QKS);
    float* mrow = Ps + QT * PSS;
    float* lrow = mrow + QT;
    float* arow = lrow + QT;

    const int tid = threadIdx.x;
    const int lane = tid & 31;
    const int wid = tid >> 5;
    const int head = blockIdx.y;
    const int q0 = blockIdx.x * QT;
    const int seqlen = seq_lens[0];
    const int hoff = head * HD;

    const int wm_s = (wid >> 2) * 32;
    const int wn_s = (wid & 3) * 16;
    const int wm_o = (wid >> 2) * 32;
    const int wn_o = (wid & 3) * 32;

#pragma unroll
    for (int u = 0; u < 8; u++) {
        int slot = tid + 256 * u;
        int r = slot >> 5;
        int qq = (slot & 31) * 4;
        int grow = q0 + r;
        float4 val = (grow < S_LEN) ? *(const float4*)(q + (size_t)grow * DIM + hoff + qq)
                                    : make_float4(0.f, 0.f, 0.f, 0.f);
        *(float4*)&Qs[r * QKS + qq] = val;
    }
    if (tid < QT) { mrow[tid] = -3.0e38f; lrow[tid] = 0.f; }

    float oacc[2][4][4];
#pragma unroll
    for (int a = 0; a < 2; a++)
#pragma unroll
        for (int b = 0; b < 4; b++)
#pragma unroll
            for (int c = 0; c < 4; c++) oacc[a][b][c] = 0.f;

    const float scale = 0.08838834764831845f;

    const int ldr = tid >> 5;
    const int ldq = (tid & 31) * 4;

    float4 kvreg[8];
#pragma unroll
    for (int u = 0; u < 8; u++) {
        int r = ldr + u * 8;
        kvreg[u] = (r < seqlen) ? *(const float4*)(k + (size_t)r * DIM + hoff + ldq)
                                : make_float4(0.f, 0.f, 0.f, 0.f);
    }

    for (int kv0 = 0; kv0 < seqlen; kv0 += 64) {
        __syncthreads();
#pragma unroll
        for (int u = 0; u < 8; u++) {
            int r = ldr + u * 8;
            *(float4*)&KVs[r * QKS + ldq] = kvreg[u];
        }
        __syncthreads();

#pragma unroll
        for (int u = 0; u < 8; u++) {
            int r = kv0 + ldr + u * 8;
            kvreg[u] = (r < seqlen) ? *(const float4*)(v + (size_t)r * DIM + hoff + ldq)
                                    : make_float4(0.f, 0.f, 0.f, 0.f);
        }

        float sacc[2][2][4];
#pragma unroll
        for (int a = 0; a < 2; a++)
#pragma unroll
            for (int b = 0; b < 2; b++)
#pragma unroll
                for (int c = 0; c < 4; c++) sacc[a][b][c] = 0.f;

#pragma unroll
        for (int ks = 0; ks < 16; ks++) {
            const int c = ks * 8 + (lane & 3);
            uint32_t af[2][4];
#pragma unroll
            for (int mt = 0; mt < 2; mt++) {
                int row = wm_s + mt * 16 + (lane >> 2);
                af[mt][0] = Qs[row * QKS + c];
                af[mt][1] = Qs[(row + 8) * QKS + c];
                af[mt][2] = Qs[row * QKS + c + 4];
                af[mt][3] = Qs[(row + 8) * QKS + c + 4];
            }
            uint32_t bf[2][2];
#pragma unroll
            for (int nt = 0; nt < 2; nt++) {
                int n = wn_s + nt * 8 + (lane >> 2);
                bf[nt][0] = KVs[n * QKS + c];
                bf[nt][1] = KVs[n * QKS + c + 4];
            }
#pragma unroll
            for (int mt = 0; mt < 2; mt++)
#pragma unroll
                for (int nt = 0; nt < 2; nt++)
                    mma8(sacc[mt][nt][0], sacc[mt][nt][1], sacc[mt][nt][2], sacc[mt][nt][3],
                         af[mt][0], af[mt][1], af[mt][2], af[mt][3],
                         bf[nt][0], bf[nt][1]);
        }

#pragma unroll
        for (int mt = 0; mt < 2; mt++) {
            int row = wm_s + mt * 16 + (lane >> 2);
#pragma unroll
            for (int nt = 0; nt < 2; nt++) {
                int col = wn_s + nt * 8 + (lane & 3) * 2;
                bool m0 = (kv0 + col) >= seqlen;
                bool m1 = (kv0 + col + 1) >= seqlen;
                float2 v0 = make_float2(m0 ? -1e30f : sacc[mt][nt][0] * scale,
                                        m1 ? -1e30f : sacc[mt][nt][1] * scale);
                float2 v1 = make_float2(m0 ? -1e30f : sacc[mt][nt][2] * scale,
                                        m1 ? -1e30f : sacc[mt][nt][3] * scale);
                *(float2*)(Ps + row * PSS + col) = v0;
                *(float2*)(Ps + (row + 8) * PSS + col) = v1;
            }
        }
        __syncthreads();

#pragma unroll
        for (int u = 0; u < 8; u++) {
            int r = ldr + u * 8;
            *(float4*)&KVs[r * QKS + ldq] = kvreg[u];
        }

        if (kv0 + 64 < seqlen) {
#pragma unroll
            for (int u = 0; u < 8; u++) {
                int r = kv0 + 64 + ldr + u * 8;
                kvreg[u] = (r < seqlen) ? *(const float4*)(k + (size_t)r * DIM + hoff + ldq)
                                        : make_float4(0.f, 0.f, 0.f, 0.f);
            }
        }

        {
            const int i = tid >> 2, sub = tid & 3;
            const int jbase = sub * 16;
            float mold = mrow[i];
            float mloc = -3.0e38f;
#pragma unroll
            for (int jj = 0; jj < 16; jj++)
                mloc = fmaxf(mloc, Ps[i * PSS + jbase + jj]);
            mloc = fmaxf(mloc, __shfl_xor_sync(0xffffffffu, mloc, 1));
            mloc = fmaxf(mloc, __shfl_xor_sync(0xffffffffu, mloc, 2));
            float mnew = fmaxf(mold, mloc);
            float sum = 0.f;
#pragma unroll
            for (int jj = 0; jj < 16; jj++) {
                float p = __expf(Ps[i * PSS + jbase + jj] - mnew);
                Ps[i * PSS + jbase + jj] = p;
                sum += p;
            }
            sum += __shfl_xor_sync(0xffffffffu, sum, 1);
            sum += __shfl_xor_sync(0xffffffffu, sum, 2);
            if (sub == 0) {
                float al = __expf(mold - mnew);
                arow[i] = al;
                lrow[i] = lrow[i] * al + sum;
                mrow[i] = mnew;
            }
        }
        __syncthreads();

#pragma unroll
        for (int mt = 0; mt < 2; mt++) {
            int row = wm_o + mt * 16 + (lane >> 2);
            float al0 = arow[row];
            float al1 = arow[row + 8];
#pragma unroll
            for (int nt = 0; nt < 4; nt++) {
                oacc[mt][nt][0] *= al0;
                oacc[mt][nt][1] *= al0;
                oacc[mt][nt][2] *= al1;
                oacc[mt][nt][3] *= al1;
            }
        }
#pragma unroll
        for (int ks = 0; ks < 8; ks++) {
            const int c = ks * 8 + (lane & 3);
            uint32_t paf[2][4];
#pragma unroll
            for (int mt = 0; mt < 2; mt++) {
                int row = wm_o + mt * 16 + (lane >> 2);
                paf[mt][0] = __float_as_uint(Ps[row * PSS + c]);
                paf[mt][1] = __float_as_uint(Ps[(row + 8) * PSS + c]);
                paf[mt][2] = __float_as_uint(Ps[row * PSS + c + 4]);
                paf[mt][3] = __float_as_uint(Ps[(row + 8) * PSS + c + 4]);
            }
#pragma unroll
            for (int nt = 0; nt < 4; nt++) {
                int n = wn_o + nt * 8 + (lane >> 2);
                uint32_t b0 = KVs[c * QKS + n];
                uint32_t b1 = KVs[(c + 4) * QKS + n];
#pragma unroll
                for (int mt = 0; mt < 2; mt++)
                    mma8(oacc[mt][nt][0], oacc[mt][nt][1], oacc[mt][nt][2], oacc[mt][nt][3],
                         paf[mt][0], paf[mt][1], paf[mt][2], paf[mt][3], b0, b1);
            }
        }
    }

#pragma unroll
    for (int mt = 0; mt < 2; mt++) {
        int lrow0 = wm_o + mt * 16 + (lane >> 2);
        int grow0 = q0 + lrow0;
        float inv0 = 1.0f / lrow[lrow0];
        float inv1 = 1.0f / lrow[lrow0 + 8];
#pragma unroll
        for (int nt = 0; nt < 4; nt++) {
            int col = hoff + wn_o + nt * 8 + (lane & 3) * 2;
            if (grow0 < S_LEN) {
                float2 v0 = make_float2(
                    __uint_as_float(f2tf(oacc[mt][nt][0] * inv0)),
                    __uint_as_float(f2tf(oacc[mt][nt][1] * inv0)));
                *(float2*)(o + (size_t)grow0 * DIM + col) = v0;
            }
            if (grow0 + 8 < S_LEN) {
                float2 v1 = make_float2(
                    __uint_as_float(f2tf(oacc[mt][nt][2] * inv1)),
                    __uint_as_float(f2tf(oacc[mt][nt][3] * inv1)));
                *(float2*)(o + (size_t)(grow0 + 8) * DIM + col) = v1;
            }
        }
    }
}

// ---------------------------------------------------------------------------
extern "C" void kernel_launch(void* const* d_in, const int* in_sizes, int n_in,
                              void* d_out, int out_size)
{
    const float* x  = (const float*)d_in[0];
    const float* wq = (const float*)d_in[1];
    const float* bq = (const float*)d_in[2];
    const float* wk = (const float*)d_in[3];
    const float* bk = (const float*)d_in[4];
    const float* wv = (const float*)d_in[5];
    const float* bv = (const float*)d_in[6];
    const float* wo = (const float*)d_in[7];
    const float* bo = (const float*)d_in[8];
    const float* gq = (const float*)d_in[9];
    const float* gk = (const float*)d_in[10];
    const int* seq_lens = (const int*)d_in[12];
    float* out = (float*)d_out;

    float *qp, *kp, *vp, *op, *xp, *wqp, *wkp, *wvp, *wop;
    cudaGetSymbolAddress((void**)&qp, g_q);
    cudaGetSymbolAddress((void**)&kp, g_k);
    cudaGetSymbolAddress((void**)&vp, g_v);
    cudaGetSymbolAddress((void**)&op, g_o);
    cudaGetSymbolAddress((void**)&xp, g_x);
    cudaGetSymbolAddress((void**)&wqp, g_wq);
    cudaGetSymbolAddress((void**)&wkp, g_wk);
    cudaGetSymbolAddress((void**)&wvp, g_wv);
    cudaGetSymbolAddress((void**)&wop, g_wo);

    // fused pre-round of x + 4 weights
    pre_round5<<<(PR_TOTAL + 255) / 256, 256>>>(x, xp, wq, wqp, wk, wkp,
                                                wv, wvp, wo, wop);

    cudaFuncSetAttribute(gemm_nt_tf32, cudaFuncAttributeMaxDynamicSharedMemorySize,
                         G_SMEM_BYTES);

    // fused Q/K/V projections (tf32-rounded outputs)
    dim3 gqkv(DIM / 128, (S_LEN + 127) / 128, 3);
    gemm_nt_tf32<<<gqkv, 128, G_SMEM_BYTES>>>(xp, wqp, wkp, wvp, bq, bk, bv,
                                              qp, kp, vp, S_LEN, DIM, DIM, 1);

    rmsrope_kernel<<<S_LEN, 256>>>(qp, kp, gq, gk);

    cudaFuncSetAttribute(flash_tf32, cudaFuncAttributeMaxDynamicSharedMemorySize,
                         FL_SMEM_BYTES);
    flash_tf32<<<dim3((S_LEN + QT - 1) / QT, NH), 256, FL_SMEM_BYTES>>>(
        qp, kp, vp, op, seq_lens);

    // output projection (fp32 output)
    dim3 go(DIM / 128, (S_LEN + 127) / 128, 1);
    gemm_nt_tf32<<<go, 128, G_SMEM_BYTES>>>(op, wop, wop, wop, bo, bo, bo,
                                            out, out, out, S_LEN, DIM, DIM, 0);
}